// round 13
// baseline (speedup 1.0000x reference)
#include <cuda_runtime.h>

#define IMG_H 512
#define IMG_W 512

typedef unsigned long long u64;

__constant__ u64   c_k2[9];    // conv weights packed {k,k}
__constant__ float c_pw[22];   // [0]=a, [1]=b, [2..11]=g_j, [12..21]=d_j (padded)
__constant__ int   c_cnt;      // interior-unit count (even, 0..10)

__device__ u64   d_k2s[9];
__device__ float d_pws[22];
__device__ int   d_cnts;

__device__ __forceinline__ u64 pack2(float lo, float hi) {
    u64 r; asm("mov.b64 %0, {%1, %2};" : "=l"(r) : "f"(lo), "f"(hi)); return r;
}
__device__ __forceinline__ void unpack2(u64 v, float& lo, float& hi) {
    asm("mov.b64 {%0, %1}, %2;" : "=f"(lo), "=f"(hi) : "l"(v));
}
__device__ __forceinline__ u64 ffma2(u64 a, u64 b, u64 c) {
    u64 r; asm("fma.rn.f32x2 %0, %1, %2, %3;" : "=l"(r) : "l"(a), "l"(b), "l"(c)); return r;
}
__device__ __forceinline__ u64 fmul2(u64 a, u64 b) {
    u64 r; asm("mul.rn.f32x2 %0, %1, %2;" : "=l"(r) : "l"(a), "l"(b)); return r;
}

// s(g) = a*g + b + sum_{j<cnt} d_j*|g - g_j|  (exact rewrite of the ReLU MLP on g in [0,1])
__global__ void prep_kernel(const float* __restrict__ k,
                            const float* __restrict__ w1,
                            const float* __restrict__ b1,
                            const float* __restrict__ w2) {
    if (threadIdx.x != 0 || blockIdx.x != 0) return;
    for (int i = 0; i < 9; ++i) d_k2s[i] = pack2(k[i], k[i]);
    float a = 0.0f, b = 0.0f;
    int cnt = 0;
    float gj[10], dj[10];
    for (int j = 0; j < 10; ++j) {
        float W1 = w1[j], B1 = b1[j], W2 = w2[j];
        a += 0.5f * W2 * W1;
        b += 0.5f * W2 * B1;
        bool always_on  = (B1 >= 0.0f) && (W1 + B1 >= 0.0f);
        bool always_off = (B1 <= 0.0f) && (W1 + B1 <= 0.0f);
        if (always_on)       { a += 0.5f * W2 * W1; b += 0.5f * W2 * B1; }
        else if (always_off) { a -= 0.5f * W2 * W1; b -= 0.5f * W2 * B1; }
        else { gj[cnt] = -B1 / W1; dj[cnt] = 0.5f * W2 * fabsf(W1); cnt++; }
    }
    if (cnt & 1) { gj[cnt] = 0.0f; dj[cnt] = 0.0f; cnt++; }
    d_pws[0] = a; d_pws[1] = b;
    for (int j = 0; j < 10; ++j) {
        d_pws[2 + j]  = (j < cnt) ? gj[j] : 0.0f;
        d_pws[12 + j] = (j < cnt) ? dj[j] : 0.0f;
    }
    d_cnts = cnt;
}

#define L2E 1.4426950408889634f

template <int N>
__device__ __forceinline__ float act(float v) {
    float q = fmaf(v, -L2E, 2.0f * L2E);
    q = fmaf(q, v, -L2E);                                     // -L2E*(v-1)^2
    float g; asm("ex2.approx.f32 %0, %1;" : "=f"(g) : "f"(q));
    float s = fmaf(c_pw[0], g, c_pw[1]);
#pragma unroll
    for (int j = 0; j < N; ++j)
        s = fmaf(c_pw[12 + j], fabsf(g - c_pw[2 + j]), s);
    float e; float m = s * -L2E;
    asm("ex2.approx.f32 %0, %1;" : "=f"(e) : "f"(m));         // exp(-s)
    float r;
    asm("rcp.approx.f32 %0, %1;" : "=f"(r) : "f"(1.0f + e));
    return r - 0.5f;                                          // sigmoid(s)-0.5
}

// Geometry: output tile 64 cols x 32 rows. Smem coord: col c <-> gc = cb+(c-4),
// row r <-> gy = y0+(r-2). S0 holds input rows 0..35, cols 2..69. S1 holds step1.
#define TILE_W  64
#define TILE_H  32
#define SSTRIDE 72
#define SROWS   36

// one NCA update of the pixel pair at smem (r, c), reading buffer S
template <int N>
__device__ __forceinline__ void nca_pair(const float* __restrict__ S, int r, int c,
                                         float& o0, float& o1) {
    const float* p0 = S + (r - 1) * SSTRIDE + c;
    const float* p1 = S + (r    ) * SSTRIDE + c;
    const float* p2 = S + (r + 1) * SSTRIDE + c;
    float2 m0 = *reinterpret_cast<const float2*>(p0);
    float2 m1 = *reinterpret_cast<const float2*>(p1);
    float2 m2 = *reinterpret_cast<const float2*>(p2);
    u64 A0 = pack2(p0[-1], m0.x), A1 = pack2(m0.x, m0.y), A2 = pack2(m0.y, p0[2]);
    u64 B0 = pack2(p1[-1], m1.x), B1 = pack2(m1.x, m1.y), B2 = pack2(m1.y, p1[2]);
    u64 C0 = pack2(p2[-1], m2.x), C1 = pack2(m2.x, m2.y), C2 = pack2(m2.y, p2[2]);
    u64 v = fmul2(c_k2[0], A0);
    v = ffma2(c_k2[1], A1, v);
    v = ffma2(c_k2[2], A2, v);
    v = ffma2(c_k2[3], B0, v);
    v = ffma2(c_k2[4], B1, v);
    v = ffma2(c_k2[5], B2, v);
    v = ffma2(c_k2[6], C0, v);
    v = ffma2(c_k2[7], C1, v);
    v = ffma2(c_k2[8], C2, v);
    float f0, f1;
    unpack2(v, f0, f1);
    o0 = m1.x + act<N>(f0);     // residual update
    o1 = m1.y + act<N>(f1);
}

template <int N, bool TWO>
__device__ __forceinline__ void fused_tile(const float* __restrict__ img,
                                           float* __restrict__ out1,
                                           float* __restrict__ out2,
                                           float* __restrict__ S0,
                                           float* __restrict__ S1,
                                           int cb, int y0, int tid) {
    // ---- stage input tile (+2 halo) into S0 ----
#pragma unroll
    for (int i = tid; i < SROWS * (TILE_W / 4); i += 256) {   // interior quads
        int r = i >> 4, q = i & 15;
        int gy = y0 + r - 2;
        float4 v = make_float4(0.f, 0.f, 0.f, 0.f);
        if ((unsigned)gy < IMG_H)
            v = *reinterpret_cast<const float4*>(img + gy * IMG_W + cb + q * 4);
        *reinterpret_cast<float4*>(S0 + r * SSTRIDE + 4 + q * 4) = v;
    }
    for (int i = tid; i < SROWS * 2; i += 256) {              // 2-col halos (float2)
        int r = i >> 1, side = i & 1;
        int gy = y0 + r - 2;
        int gc = side ? (cb + TILE_W) : (cb - 2);
        float2 v = make_float2(0.f, 0.f);
        if ((unsigned)gy < IMG_H && (unsigned)gc < IMG_W)
            v = *reinterpret_cast<const float2*>(img + gy * IMG_W + gc);
        *reinterpret_cast<float2*>(S0 + r * SSTRIDE + (side ? (4 + TILE_W) : 2)) = v;
    }
    __syncthreads();

    // ---- pass 1: step s+1 on +1-halo region (rows 1..34, pair cols 2,4,..,68) ----
    // independent iterations -> LDS latency hidden by ILP
    for (int i = tid; i < 34 * 34; i += 256) {
        int rr = i / 34;
        int j  = i - rr * 34;
        int r  = 1 + rr;
        int c  = 2 + 2 * j;
        float o0, o1;
        nca_pair<N>(S0, r, c, o0, o1);
        int gy = y0 + r - 2;
        int gc = cb + c - 4;
        // SAME-padding for the next conv: zero out-of-image step1 values
        float r0 = ((unsigned)gy < IMG_H && (unsigned)gc       < IMG_W) ? o0 : 0.0f;
        float r1 = ((unsigned)gy < IMG_H && (unsigned)(gc + 1) < IMG_W) ? o1 : 0.0f;
        if (TWO)
            *reinterpret_cast<float2*>(S1 + r * SSTRIDE + c) = make_float2(r0, r1);
        // interior of this CTA's tile -> global slice s+1 (each pixel written once)
        if (r >= 2 && r <= 33 && c >= 4 && c <= 66)
            *reinterpret_cast<float2*>(out1 + gy * IMG_W + gc) = make_float2(r0, r1);
    }

    // ---- pass 2: step s+2 on the interior (rows 2..33, pair cols 4..66) ----
    if (TWO) {
        __syncthreads();
        for (int i = tid; i < 32 * 32; i += 256) {
            int r = 2 + (i >> 5);
            int c = 4 + 2 * (i & 31);
            float o0, o1;
            nca_pair<N>(S1, r, c, o0, o1);
            int gy = y0 + r - 2;
            int gc = cb + c - 4;
            *reinterpret_cast<float2*>(out2 + gy * IMG_W + gc) = make_float2(o0, o1);
        }
    }
}

template <bool TWO>
__global__ __launch_bounds__(256, 7) void step_kernel(const float* __restrict__ in,
                                                      float* __restrict__ out1,
                                                      float* __restrict__ out2) {
    __shared__ float S0[SROWS * SSTRIDE];
    __shared__ float S1[SROWS * SSTRIDE];
    const int cb = blockIdx.x * TILE_W;
    const int y0 = blockIdx.y * TILE_H;
    const int b  = blockIdx.z;
    const int tid = threadIdx.x;

    const float* img = in   + (size_t)b * (IMG_H * IMG_W);
    float* o1        = out1 + (size_t)b * (IMG_H * IMG_W);
    float* o2        = out2 + (size_t)b * (IMG_H * IMG_W);

    const int n = c_cnt;                     // uniform dispatch on interior-unit count
    if      (n == 0)  fused_tile<0 , TWO>(img, o1, o2, S0, S1, cb, y0, tid);
    else if (n == 2)  fused_tile<2 , TWO>(img, o1, o2, S0, S1, cb, y0, tid);
    else if (n == 4)  fused_tile<4 , TWO>(img, o1, o2, S0, S1, cb, y0, tid);
    else if (n == 6)  fused_tile<6 , TWO>(img, o1, o2, S0, S1, cb, y0, tid);
    else if (n == 8)  fused_tile<8 , TWO>(img, o1, o2, S0, S1, cb, y0, tid);
    else              fused_tile<10, TWO>(img, o1, o2, S0, S1, cb, y0, tid);
}

extern "C" void kernel_launch(void* const* d_in, const int* in_sizes, int n_in,
                              void* d_out, int out_size) {
    const float* x  = (const float*)d_in[0];
    const float* k  = (const float*)d_in[1];
    const float* w1 = (const float*)d_in[2];
    const float* b1 = (const float*)d_in[3];
    const float* w2 = (const float*)d_in[4];
    float* out = (float*)d_out;

    const int npix  = in_sizes[0];
    const int B     = npix / (IMG_H * IMG_W);
    const int steps = out_size / npix - 1;

    // Build derived params on device, then stage into constant memory
    // (real device addresses via cudaGetSymbolAddress — not host shadows).
    prep_kernel<<<1, 32>>>(k, w1, b1, w2);
    void *pk2 = nullptr, *ppw = nullptr, *pcnt = nullptr;
    cudaGetSymbolAddress(&pk2,  d_k2s);
    cudaGetSymbolAddress(&ppw,  d_pws);
    cudaGetSymbolAddress(&pcnt, d_cnts);
    cudaMemcpyToSymbolAsync(c_k2,  pk2,  9 * sizeof(u64),    0, cudaMemcpyDeviceToDevice, 0);
    cudaMemcpyToSymbolAsync(c_pw,  ppw,  22 * sizeof(float), 0, cudaMemcpyDeviceToDevice, 0);
    cudaMemcpyToSymbolAsync(c_cnt, pcnt, sizeof(int),        0, cudaMemcpyDeviceToDevice, 0);

    // Slice 0 of the output is the initial state
    cudaMemcpyAsync(out, x, (size_t)npix * sizeof(float), cudaMemcpyDeviceToDevice, 0);

    dim3 blk(256, 1, 1);
    dim3 grd(IMG_W / TILE_W, IMG_H / TILE_H, B);   // (8, 16, B)

    int s = 0;
    while (steps - s >= 2) {
        step_kernel<true><<<grd, blk>>>(out + (size_t)s * npix,
                                        out + (size_t)(s + 1) * npix,
                                        out + (size_t)(s + 2) * npix);
        s += 2;
    }
    if (s < steps) {
        step_kernel<false><<<grd, blk>>>(out + (size_t)s * npix,
                                         out + (size_t)(s + 1) * npix,
                                         out + (size_t)(s + 1) * npix);
    }
}

// round 15
// speedup vs baseline: 2.3073x; 2.3073x over previous
#include <cuda_runtime.h>

#define IMG_H 512
#define IMG_W 512

typedef unsigned long long u64;

__constant__ u64   c_k2[9];    // conv weights packed {k,k}
__constant__ float c_pw[22];   // [0]=a/2, [1]=b/2, [2..11]=g_j, [12..21]=d_j/2
__constant__ int   c_cnt;      // interior-unit count (even, 0..10)

__device__ u64   d_k2s[9];
__device__ float d_pws[22];
__device__ int   d_cnts;

__device__ __forceinline__ u64 pack2(float lo, float hi) {
    u64 r; asm("mov.b64 %0, {%1, %2};" : "=l"(r) : "f"(lo), "f"(hi)); return r;
}
__device__ __forceinline__ void unpack2(u64 v, float& lo, float& hi) {
    asm("mov.b64 {%0, %1}, %2;" : "=f"(lo), "=f"(hi) : "l"(v));
}
__device__ __forceinline__ u64 ffma2(u64 a, u64 b, u64 c) {
    u64 r; asm("fma.rn.f32x2 %0, %1, %2, %3;" : "=l"(r) : "l"(a), "l"(b), "l"(c)); return r;
}
__device__ __forceinline__ u64 fmul2(u64 a, u64 b) {
    u64 r; asm("mul.rn.f32x2 %0, %1, %2;" : "=l"(r) : "l"(a), "l"(b)); return r;
}

// s(g)/2 = a2*g + b2 + sum_j d2_j*|g - g_j|  with a2,b2,d2 = half of the exact
// abs-form rewrite of the ReLU MLP on g in [0,1]. Then act = 0.5*tanh(s/2).
__global__ void prep_kernel(const float* __restrict__ k,
                            const float* __restrict__ w1,
                            const float* __restrict__ b1,
                            const float* __restrict__ w2) {
    if (threadIdx.x != 0 || blockIdx.x != 0) return;
    for (int i = 0; i < 9; ++i) d_k2s[i] = pack2(k[i], k[i]);
    float a = 0.0f, b = 0.0f;
    int cnt = 0;
    float gj[10], dj[10];
    for (int j = 0; j < 10; ++j) {
        float W1 = w1[j], B1 = b1[j], W2 = w2[j];
        a += 0.5f * W2 * W1;
        b += 0.5f * W2 * B1;
        bool always_on  = (B1 >= 0.0f) && (W1 + B1 >= 0.0f);
        bool always_off = (B1 <= 0.0f) && (W1 + B1 <= 0.0f);
        if (always_on)       { a += 0.5f * W2 * W1; b += 0.5f * W2 * B1; }
        else if (always_off) { a -= 0.5f * W2 * W1; b -= 0.5f * W2 * B1; }
        else { gj[cnt] = -B1 / W1; dj[cnt] = 0.5f * W2 * fabsf(W1); cnt++; }
    }
    if (cnt & 1) { gj[cnt] = 0.0f; dj[cnt] = 0.0f; cnt++; }
    d_pws[0] = 0.5f * a;           // halve for the tanh form
    d_pws[1] = 0.5f * b;
    for (int j = 0; j < 10; ++j) {
        d_pws[2 + j]  = (j < cnt) ? gj[j] : 0.0f;
        d_pws[12 + j] = (j < cnt) ? (0.5f * dj[j]) : 0.0f;
    }
    d_cnts = cnt;
}

#define L2E 1.4426950408889634f

// returns tanh(s/2); caller applies x + 0.5*th  (== x + sigmoid(s) - 0.5)
template <int N>
__device__ __forceinline__ float act_th(float v) {
    float q = fmaf(v, -L2E, 2.0f * L2E);
    q = fmaf(q, v, -L2E);                                     // -L2E*(v-1)^2
    float g; asm("ex2.approx.f32 %0, %1;" : "=f"(g) : "f"(q));
    float h = fmaf(c_pw[0], g, c_pw[1]);
#pragma unroll
    for (int j = 0; j < N; ++j)
        h = fmaf(c_pw[12 + j], fabsf(g - c_pw[2 + j]), h);
    float th; asm("tanh.approx.f32 %0, %1;" : "=f"(th) : "f"(h));
    return th;
}

// Tile geometry: CTA covers 64 cols x 64 rows. blockDim=(32,8), 2 cols x 8 rows/thread.
// Smem stage: 66 rows x 72 cols (interior at col 4, halos at cols 3 and 68).
#define TILE_W   64
#define TILE_H   64
#define SROWS    66
#define SSTRIDE  72

template <int N>
__device__ __forceinline__ void run_tile(const float* __restrict__ img,
                                         float* __restrict__ oimg,
                                         float* __restrict__ sm,
                                         int cb, int y0) {
    const int tid = threadIdx.y * 32 + threadIdx.x;

    // ---- stage tile + halo into smem (bulk LDG.128, latency amortized) ----
    {
        for (int i = tid; i < SROWS * (TILE_W / 4); i += 256) {
            int r = i >> 4, q = i & 15;
            int gy = y0 - 1 + r;
            float4 v = make_float4(0.f, 0.f, 0.f, 0.f);
            if ((unsigned)gy < IMG_H)
                v = *reinterpret_cast<const float4*>(img + gy * IMG_W + cb + q * 4);
            *reinterpret_cast<float4*>(sm + r * SSTRIDE + 4 + q * 4) = v;
        }
        for (int i = tid; i < SROWS * 2; i += 256) {
            int r = i >> 1, side = i & 1;
            int gy = y0 - 1 + r;
            int gc = side ? (cb + TILE_W) : (cb - 1);
            float v = 0.0f;
            if ((unsigned)gy < IMG_H && (unsigned)gc < IMG_W)
                v = __ldg(img + gy * IMG_W + gc);
            sm[r * SSTRIDE + (side ? (4 + TILE_W) : 3)] = v;
        }
    }
    __syncthreads();

    // ---- compute: 2 cols x 8 rows/thread; 3-row window, pipelined LDS ----
    const int tx = threadIdx.x;
    const int ty = threadIdx.y;
    const int colb = 4 + 2 * tx;
    const int rbase = ty * 8;               // smem row of (first output row - 1)

    u64 win[3][3];
    float tl, tx0, tx1, tr;                 // raw prefetch regs (one row)

    auto fetch_raw = [&](int r) {           // issue LDS, no packing yet
        const float* row = sm + r * SSTRIDE;
        float2 v = *reinterpret_cast<const float2*>(row + colb);
        tl = row[colb - 1];
        tr = row[colb + 2];
        tx0 = v.x; tx1 = v.y;
    };
    auto commit = [&](u64* P) {             // pack raw row into window slot
        P[0] = pack2(tl,  tx0);
        P[1] = pack2(tx0, tx1);
        P[2] = pack2(tx1, tr);
    };

    fetch_raw(rbase);     commit(win[0]);
    fetch_raw(rbase + 1); commit(win[1]);
    fetch_raw(rbase + 2);                   // row for iteration 0, committed below

    const int gc = cb + 2 * tx;
#pragma unroll
    for (int t = 0; t < 8; ++t) {
        u64* rm = win[(t + 0) % 3];
        u64* rc = win[(t + 1) % 3];
        u64* rp = win[(t + 2) % 3];
        commit(rp);                          // row t+2 (loaded last iteration)
        if (t < 7) fetch_raw(rbase + t + 3); // prefetch for next iteration

        u64 v = fmul2(c_k2[0], rm[0]);
        v = ffma2(c_k2[1], rm[1], v);
        v = ffma2(c_k2[2], rm[2], v);
        v = ffma2(c_k2[3], rc[0], v);
        v = ffma2(c_k2[4], rc[1], v);
        v = ffma2(c_k2[5], rc[2], v);
        v = ffma2(c_k2[6], rp[0], v);
        v = ffma2(c_k2[7], rp[1], v);
        v = ffma2(c_k2[8], rp[2], v);

        float f0, f1, x0, x1;
        unpack2(v, f0, f1);
        unpack2(rc[1], x0, x1);

        float2 o;
        o.x = fmaf(0.5f, act_th<N>(f0), x0);
        o.y = fmaf(0.5f, act_th<N>(f1), x1);
        *reinterpret_cast<float2*>(oimg + (y0 + ty * 8 + t) * IMG_W + gc) = o;
    }
}

__global__ __launch_bounds__(256, 7) void step_kernel(const float* __restrict__ in,
                                                      float* __restrict__ out) {
    __shared__ float sm[SROWS * SSTRIDE];
    const int cb = blockIdx.x * TILE_W;
    const int y0 = blockIdx.y * TILE_H;
    const int b  = blockIdx.z;

    const float* img  = in  + (size_t)b * (IMG_H * IMG_W);
    float*       oimg = out + (size_t)b * (IMG_H * IMG_W);

    const int n = c_cnt;
    if      (n == 0)  run_tile<0 >(img, oimg, sm, cb, y0);
    else if (n == 2)  run_tile<2 >(img, oimg, sm, cb, y0);
    else if (n == 4)  run_tile<4 >(img, oimg, sm, cb, y0);
    else if (n == 6)  run_tile<6 >(img, oimg, sm, cb, y0);
    else if (n == 8)  run_tile<8 >(img, oimg, sm, cb, y0);
    else              run_tile<10>(img, oimg, sm, cb, y0);
}

extern "C" void kernel_launch(void* const* d_in, const int* in_sizes, int n_in,
                              void* d_out, int out_size) {
    const float* x  = (const float*)d_in[0];
    const float* k  = (const float*)d_in[1];
    const float* w1 = (const float*)d_in[2];
    const float* b1 = (const float*)d_in[3];
    const float* w2 = (const float*)d_in[4];
    float* out = (float*)d_out;

    const int npix  = in_sizes[0];
    const int B     = npix / (IMG_H * IMG_W);
    const int steps = out_size / npix - 1;

    prep_kernel<<<1, 32>>>(k, w1, b1, w2);
    void *pk2 = nullptr, *ppw = nullptr, *pcnt = nullptr;
    cudaGetSymbolAddress(&pk2,  d_k2s);
    cudaGetSymbolAddress(&ppw,  d_pws);
    cudaGetSymbolAddress(&pcnt, d_cnts);
    cudaMemcpyToSymbolAsync(c_k2,  pk2,  9 * sizeof(u64),    0, cudaMemcpyDeviceToDevice, 0);
    cudaMemcpyToSymbolAsync(c_pw,  ppw,  22 * sizeof(float), 0, cudaMemcpyDeviceToDevice, 0);
    cudaMemcpyToSymbolAsync(c_cnt, pcnt, sizeof(int),        0, cudaMemcpyDeviceToDevice, 0);

    cudaMemcpyAsync(out, x, (size_t)npix * sizeof(float), cudaMemcpyDeviceToDevice, 0);

    dim3 blk(32, 8, 1);
    dim3 grd(IMG_W / TILE_W, IMG_H / TILE_H, B);   // (8, 8, B) = 1024 CTAs

    for (int s = 0; s < steps; ++s) {
        const float* src = out + (size_t)s       * npix;
        float*       dst = out + (size_t)(s + 1) * npix;
        step_kernel<<<grd, blk>>>(src, dst);
    }
}